// round 9
// baseline (speedup 1.0000x reference)
#include <cuda_runtime.h>
#include <cuda_bf16.h>

#define NN 20000
#define NE 100000
#define ND 128
#define ED 128
#define EIN 291
#define HH 64
#define EPB 8          // for embed/classify kernels

// mpn_step GEMM config
#define BLK_E 128      // edges per block
#define NTH   256      // threads per block
#define AP    132      // A-tile row stride in floats (16B-aligned, conflict-free)

// Scratch (device globals; no allocation allowed)
__device__ float g_nf0[NN * ND];
__device__ float g_nfA[NN * ND];
__device__ float g_nfB[NN * ND];
__device__ float g_ef0[NE * ED];
__device__ float g_ef [NE * ED];
// duplicated weights: wD[k][c] = (w[k][c], w[k][c]) packed pairs
__device__ float g_mew0D[768 * 64 * 2];
__device__ float g_mew1D[64 * 128 * 2];
__device__ float g_mnw0D[384 * 128 * 2];

// ---------------------------------------------------------------------------
// f32x2 packed helpers (Blackwell FFMA2 path — PTX only)
// ---------------------------------------------------------------------------
__device__ __forceinline__ void fma2(unsigned long long& d,
                                     unsigned long long a, unsigned long long b) {
    asm("fma.rn.f32x2 %0, %1, %2, %0;" : "+l"(d) : "l"(a), "l"(b));
}
__device__ __forceinline__ unsigned long long pk2(float lo, float hi) {
    unsigned long long r;
    asm("mov.b64 %0, {%1, %2};" : "=l"(r) : "f"(lo), "f"(hi));
    return r;
}
__device__ __forceinline__ void upk2(float& lo, float& hi, unsigned long long v) {
    asm("mov.b64 {%0, %1}, %2;" : "=f"(lo), "=f"(hi) : "l"(v));
}

// ---------------------------------------------------------------------------
// One-time weight duplication: wD[2i] = wD[2i+1] = w[i]
// ---------------------------------------------------------------------------
__global__ void dup_weights(const float* __restrict__ mew0,
                            const float* __restrict__ mew1,
                            const float* __restrict__ mnw0)
{
    const int i = blockIdx.x * blockDim.x + threadIdx.x;
    if (i < 768 * 64)  { const float v = mew0[i]; g_mew0D[2*i] = v; g_mew0D[2*i+1] = v; }
    if (i < 64 * 128)  { const float v = mew1[i]; g_mew1D[2*i] = v; g_mew1D[2*i+1] = v; }
    if (i < 384 * 128) { const float v = mnw0[i]; g_mnw0D[2*i] = v; g_mnw0D[2*i+1] = v; }
}

// ---------------------------------------------------------------------------
// Node embedding: nf0 = lin(relu(lin(x, new0)), new1)   [N,128]
// ---------------------------------------------------------------------------
__global__ void node_embed_kernel(const float* __restrict__ x,
                                  const float* __restrict__ w0, const float* __restrict__ b0,
                                  const float* __restrict__ w1, const float* __restrict__ b1)
{
    __shared__ float s_x[EPB][ND];
    __shared__ float s_h[EPB][ND];
    const int t = threadIdx.x;
    const int nb = blockIdx.x * EPB;

    #pragma unroll
    for (int r = 0; r < EPB; r++) s_x[r][t] = x[(nb + r) * ND + t];
    __syncthreads();

    float acc[EPB];
    {
        const float b = b0[t];
        #pragma unroll
        for (int r = 0; r < EPB; r++) acc[r] = b;
        #pragma unroll 4
        for (int k = 0; k < ND; k += 4) {
            float4 w4;
            w4.x = w0[(k + 0) * ND + t];
            w4.y = w0[(k + 1) * ND + t];
            w4.z = w0[(k + 2) * ND + t];
            w4.w = w0[(k + 3) * ND + t];
            #pragma unroll
            for (int r = 0; r < EPB; r++) {
                const float4 v = *(const float4*)&s_x[r][k];
                acc[r] += v.x * w4.x + v.y * w4.y + v.z * w4.z + v.w * w4.w;
            }
        }
        #pragma unroll
        for (int r = 0; r < EPB; r++) s_h[r][t] = fmaxf(acc[r], 0.f);
    }
    __syncthreads();
    {
        const float b = b1[t];
        #pragma unroll
        for (int r = 0; r < EPB; r++) acc[r] = b;
        #pragma unroll 4
        for (int k = 0; k < ND; k += 4) {
            float4 w4;
            w4.x = w1[(k + 0) * ND + t];
            w4.y = w1[(k + 1) * ND + t];
            w4.z = w1[(k + 2) * ND + t];
            w4.w = w1[(k + 3) * ND + t];
            #pragma unroll
            for (int r = 0; r < EPB; r++) {
                const float4 v = *(const float4*)&s_h[r][k];
                acc[r] += v.x * w4.x + v.y * w4.y + v.z * w4.z + v.w * w4.w;
            }
        }
        #pragma unroll
        for (int r = 0; r < EPB; r++) g_nf0[(nb + r) * ND + t] = acc[r];
    }
}

// ---------------------------------------------------------------------------
// Edge embedding: ef0 = lin(relu(lin(edge_attr, eew0)), eew1)   [E,128]
// ---------------------------------------------------------------------------
__global__ void edge_embed_kernel(const float* __restrict__ ea,
                                  const float* __restrict__ w0, const float* __restrict__ b0,
                                  const float* __restrict__ w1, const float* __restrict__ b1)
{
    __shared__ float s_in[EPB][EIN + 1];
    __shared__ float s_part[128][EPB + 1];
    __shared__ float s_h[EPB][HH];
    const int t = threadIdx.x;
    const int eb = blockIdx.x * EPB;

    #pragma unroll
    for (int r = 0; r < EPB; r++) {
        const float* row = ea + (size_t)(eb + r) * EIN;
        for (int k = t; k < EIN; k += 128) s_in[r][k] = row[k];
    }
    __syncthreads();

    const int c = t & 63, half = t >> 6;
    const int ks = half ? 146 : 0;
    const int ke = half ? EIN : 146;
    float acc[EPB];
    #pragma unroll
    for (int r = 0; r < EPB; r++) acc[r] = 0.f;
    for (int k = ks; k < ke; k++) {
        const float w = w0[k * HH + c];
        #pragma unroll
        for (int r = 0; r < EPB; r++) acc[r] += s_in[r][k] * w;
    }
    #pragma unroll
    for (int r = 0; r < EPB; r++) s_part[t][r] = acc[r];
    __syncthreads();

    if (t < HH) {
        const float b = b0[t];
        #pragma unroll
        for (int r = 0; r < EPB; r++)
            s_h[r][t] = fmaxf(s_part[t][r] + s_part[t + 64][r] + b, 0.f);
    }
    __syncthreads();

    {
        const float b = b1[t];
        float a2[EPB];
        #pragma unroll
        for (int r = 0; r < EPB; r++) a2[r] = b;
        #pragma unroll 4
        for (int k = 0; k < HH; k += 4) {
            float4 w4;
            w4.x = w1[(k + 0) * ED + t];
            w4.y = w1[(k + 1) * ED + t];
            w4.z = w1[(k + 2) * ED + t];
            w4.w = w1[(k + 3) * ED + t];
            #pragma unroll
            for (int r = 0; r < EPB; r++) {
                const float4 v = *(const float4*)&s_h[r][k];
                a2[r] += v.x * w4.x + v.y * w4.y + v.z * w4.z + v.w * w4.w;
            }
        }
        #pragma unroll
        for (int r = 0; r < EPB; r++) {
            const int e = eb + r;
            g_ef0[e * ED + t] = a2[r];
            g_ef [e * ED + t] = a2[r];
        }
    }
}

// ---------------------------------------------------------------------------
__global__ void zero_nf_kernel(int sel)
{
    float* p = sel ? g_nfB : g_nfA;
    const int i = blockIdx.x * blockDim.x + threadIdx.x;
    if (i < NN * ND) p[i] = 0.f;
}

// ---------------------------------------------------------------------------
// One message-passing step: three register-tiled GEMMs over 128-edge tiles.
// A gathered transposed into smem per 64-k chunk; B staged as PRE-DUPLICATED
// (w,w) pairs (no per-k packing movs); f32x2 FMA with edge pairs in lanes.
//   phase: 0: nf_in=g_nf0 out A | 1: in A out B | 2: in B out A | 3: in A
// ---------------------------------------------------------------------------
__global__ void __launch_bounds__(NTH)
mpn_step_kernel(const int* __restrict__ ei,
                const float* __restrict__ meb0,
                const float* __restrict__ meb1,
                const float* __restrict__ mnb0,
                int phase, int compute_msg)
{
    extern __shared__ float smf[];
    float* sA  = smf;                       // [64][AP] transposed A chunk
    float* sB  = smf + 64 * AP;             // duplicated B chunk, up to 64x128x2
    int*   sRi = (int*)(sB + 64 * 256);     // target node per edge
    int*   sRj = sRi + BLK_E;               // source node per edge
    int*   sRe = sRj + BLK_E;               // (clamped) global edge id

    const float* __restrict__ nf_in =
        (phase == 0) ? g_nf0 : ((phase & 1) ? g_nfA : g_nfB);
    float* __restrict__ nf_out = (phase & 1) ? g_nfB : g_nfA;

    const int t  = threadIdx.x;
    const int eb = blockIdx.x * BLK_E;
    const int cg = t & 15;        // col-group
    const int eg = t >> 4;        // edge-group (16 groups x 8 edges)
    const int e0 = eg * 8;
    const int ge = t & 127;       // gather edge
    const int gh = t >> 7;        // gather k-half (0/1)

    if (t < BLK_E) {
        int e = eb + t; if (e > NE - 1) e = NE - 1;
        sRe[t] = e;
        sRj[t] = ei[e];
        sRi[t] = ei[NE + e];
    }

    // ================= Phase 1: h = relu(A768 @ mew0 + meb0), 64 cols ======
    unsigned long long acc1[4][4];
    #pragma unroll
    for (int c = 0; c < 4; c++) {
        const float b = meb0[cg * 4 + c];
        const unsigned long long bp = pk2(b, b);
        #pragma unroll
        for (int p = 0; p < 4; p++) acc1[p][c] = bp;
    }

    #pragma unroll 1
    for (int ch = 0; ch < 12; ch++) {
        __syncthreads();
        // gather A chunk (rows 64*ch .. +63 of the concat input), transposed
        {
            const int sel = ch >> 2;   // 0: idx=i, 1: idx=j, 2: idx=e
            const int sub = ch & 3;
            const float* src;
            const int* ridx;
            if (sel == 0)      { src = (sub < 2) ? g_nf0 : nf_in; ridx = sRi; }
            else if (sel == 1) { src = (sub < 2) ? g_nf0 : nf_in; ridx = sRj; }
            else               { src = (sub < 2) ? g_ef0 : g_ef;  ridx = sRe; }
            const int koff = (sub & 1) * 64;
            const int row  = ridx[ge];
            const float4* p = (const float4*)(src + (size_t)row * 128 + koff + gh * 32);
            #pragma unroll
            for (int q = 0; q < 8; q++) {
                const float4 v = p[q];
                float* d = sA + (gh * 32 + q * 4) * AP + ge;
                d[0] = v.x; d[AP] = v.y; d[2 * AP] = v.z; d[3 * AP] = v.w;
            }
        }
        // stage duplicated B chunk: 64 k-rows x 64 cols x2 (= 32 KB)
        {
            const float4* w = (const float4*)(g_mew0D + (size_t)ch * 64 * 128);
            float4* d = (float4*)sB;
            #pragma unroll
            for (int r = 0; r < 8; r++) d[t + r * NTH] = w[t + r * NTH];
        }
        __syncthreads();
        #pragma unroll 4
        for (int kk = 0; kk < 64; kk++) {
            const ulonglong2 a01 = *(const ulonglong2*)(sA + kk * AP + e0);
            const ulonglong2 a23 = *(const ulonglong2*)(sA + kk * AP + e0 + 4);
            const unsigned long long av[4] = {a01.x, a01.y, a23.x, a23.y};
            const ulonglong2 w01 = *(const ulonglong2*)(sB + kk * 128 + cg * 8);
            const ulonglong2 w23 = *(const ulonglong2*)(sB + kk * 128 + cg * 8 + 4);
            const unsigned long long wv[4] = {w01.x, w01.y, w23.x, w23.y};
            #pragma unroll
            for (int p = 0; p < 4; p++)
                #pragma unroll
                for (int c = 0; c < 4; c++)
                    fma2(acc1[p][c], av[p], wv[c]);
        }
    }

    // epilogue: relu(h) -> sA transposed [hcol][edge]; stage duplicated mew1
    __syncthreads();
    #pragma unroll
    for (int p = 0; p < 4; p++)
        #pragma unroll
        for (int c = 0; c < 4; c++) {
            float lo, hi; upk2(lo, hi, acc1[p][c]);
            sA[(cg * 4 + c) * AP + e0 + 2 * p]     = fmaxf(lo, 0.f);
            sA[(cg * 4 + c) * AP + e0 + 2 * p + 1] = fmaxf(hi, 0.f);
        }
    {
        const float4* w = (const float4*)g_mew1D;
        float4* d = (float4*)sB;
        #pragma unroll
        for (int r = 0; r < 16; r++) d[t + r * NTH] = w[t + r * NTH];
    }
    __syncthreads();

    // ================= Phase 2: ef = relu(h @ mew1 + meb1), 128 cols =======
    unsigned long long acc2[4][8];
    #pragma unroll
    for (int c = 0; c < 8; c++) {
        const float b = meb1[cg * 8 + c];
        const unsigned long long bp = pk2(b, b);
        #pragma unroll
        for (int p = 0; p < 4; p++) acc2[p][c] = bp;
    }
    #pragma unroll 2
    for (int kk = 0; kk < 64; kk++) {
        const ulonglong2 a01 = *(const ulonglong2*)(sA + kk * AP + e0);
        const ulonglong2 a23 = *(const ulonglong2*)(sA + kk * AP + e0 + 4);
        const unsigned long long av[4] = {a01.x, a01.y, a23.x, a23.y};
        const ulonglong2 wa = *(const ulonglong2*)(sB + kk * 256 + cg * 16);
        const ulonglong2 wb = *(const ulonglong2*)(sB + kk * 256 + cg * 16 + 4);
        const ulonglong2 wc = *(const ulonglong2*)(sB + kk * 256 + cg * 16 + 8);
        const ulonglong2 wd = *(const ulonglong2*)(sB + kk * 256 + cg * 16 + 12);
        const unsigned long long wv[8] =
            {wa.x, wa.y, wb.x, wb.y, wc.x, wc.y, wd.x, wd.y};
        #pragma unroll
        for (int p = 0; p < 4; p++)
            #pragma unroll
            for (int c = 0; c < 8; c++)
                fma2(acc2[p][c], av[p], wv[c]);
    }
    // epilogue: relu + store ef to global (read back by phase 3 / next step)
    #pragma unroll
    for (int p = 0; p < 4; p++) {
        float lo[8], hi[8];
        #pragma unroll
        for (int c = 0; c < 8; c++) {
            upk2(lo[c], hi[c], acc2[p][c]);
            lo[c] = fmaxf(lo[c], 0.f);
            hi[c] = fmaxf(hi[c], 0.f);
        }
        const int el0 = e0 + 2 * p;
        if (eb + el0 < NE) {
            float4* d = (float4*)(g_ef + (size_t)(eb + el0) * 128 + cg * 8);
            d[0] = make_float4(lo[0], lo[1], lo[2], lo[3]);
            d[1] = make_float4(lo[4], lo[5], lo[6], lo[7]);
        }
        if (eb + el0 + 1 < NE) {
            float4* d = (float4*)(g_ef + (size_t)(eb + el0 + 1) * 128 + cg * 8);
            d[0] = make_float4(hi[0], hi[1], hi[2], hi[3]);
            d[1] = make_float4(hi[4], hi[5], hi[6], hi[7]);
        }
    }

    if (!compute_msg) return;

    // ====== Phase 3: msg = relu([x_i | ef] @ mnw0 + mnb0); scatter-add =====
    unsigned long long acc3[4][8];
    #pragma unroll
    for (int c = 0; c < 8; c++) {
        const float b = mnb0[cg * 8 + c];
        const unsigned long long bp = pk2(b, b);
        #pragma unroll
        for (int p = 0; p < 4; p++) acc3[p][c] = bp;
    }
    #pragma unroll 1
    for (int ch = 0; ch < 6; ch++) {
        __syncthreads();
        {
            const float* src;
            const int* ridx;
            if (ch < 2)      { src = g_nf0; ridx = sRi; }
            else if (ch < 4) { src = nf_in; ridx = sRi; }
            else             { src = g_ef;  ridx = sRe; }
            const int koff = (ch & 1) * 64;
            const int row  = ridx[ge];
            const float4* p = (const float4*)(src + (size_t)row * 128 + koff + gh * 32);
            #pragma unroll
            for (int q = 0; q < 8; q++) {
                const float4 v = p[q];
                float* d = sA + (gh * 32 + q * 4) * AP + ge;
                d[0] = v.x; d[AP] = v.y; d[2 * AP] = v.z; d[3 * AP] = v.w;
            }
        }
        {
            const float4* w = (const float4*)(g_mnw0D + (size_t)ch * 64 * 256);
            float4* d = (float4*)sB;
            #pragma unroll
            for (int r = 0; r < 16; r++) d[t + r * NTH] = w[t + r * NTH];
        }
        __syncthreads();
        #pragma unroll 2
        for (int kk = 0; kk < 64; kk++) {
            const ulonglong2 a01 = *(const ulonglong2*)(sA + kk * AP + e0);
            const ulonglong2 a23 = *(const ulonglong2*)(sA + kk * AP + e0 + 4);
            const unsigned long long av[4] = {a01.x, a01.y, a23.x, a23.y};
            const ulonglong2 wa = *(const ulonglong2*)(sB + kk * 256 + cg * 16);
            const ulonglong2 wb = *(const ulonglong2*)(sB + kk * 256 + cg * 16 + 4);
            const ulonglong2 wc = *(const ulonglong2*)(sB + kk * 256 + cg * 16 + 8);
            const ulonglong2 wd = *(const ulonglong2*)(sB + kk * 256 + cg * 16 + 12);
            const unsigned long long wv[8] =
                {wa.x, wa.y, wb.x, wb.y, wc.x, wc.y, wd.x, wd.y};
            #pragma unroll
            for (int p = 0; p < 4; p++)
                #pragma unroll
                for (int c = 0; c < 8; c++)
                    fma2(acc3[p][c], av[p], wv[c]);
        }
    }
    // epilogue: relu + atomic scatter-add to nf_out
    #pragma unroll
    for (int p = 0; p < 4; p++) {
        float lo[8], hi[8];
        #pragma unroll
        for (int c = 0; c < 8; c++) {
            upk2(lo[c], hi[c], acc3[p][c]);
            lo[c] = fmaxf(lo[c], 0.f);
            hi[c] = fmaxf(hi[c], 0.f);
        }
        const int el0 = e0 + 2 * p;
        if (eb + el0 < NE) {
            float* dst = nf_out + (size_t)sRi[el0] * 128 + cg * 8;
            #pragma unroll
            for (int c = 0; c < 8; c++) atomicAdd(dst + c, lo[c]);
        }
        if (eb + el0 + 1 < NE) {
            float* dst = nf_out + (size_t)sRi[el0 + 1] * 128 + cg * 8;
            #pragma unroll
            for (int c = 0; c < 8; c++) atomicAdd(dst + c, hi[c]);
        }
    }
}

// ---------------------------------------------------------------------------
// Classifier: out = lin(relu(lin(relu(lin(ef, cw0)), cw1)), cw2)  [E,1]
// ---------------------------------------------------------------------------
__global__ void classify_kernel(float* __restrict__ out,
                                const float* __restrict__ cw0, const float* __restrict__ cb0,
                                const float* __restrict__ cw1, const float* __restrict__ cb1,
                                const float* __restrict__ cw2, const float* __restrict__ cb2)
{
    __shared__ float s_ef[EPB][ED];
    __shared__ float s_h0[EPB][64];
    __shared__ float s_h1[EPB][32];
    const int t = threadIdx.x;
    const int eb = blockIdx.x * EPB;

    #pragma unroll
    for (int r = 0; r < EPB; r++) s_ef[r][t] = g_ef[(eb + r) * ED + t];
    __syncthreads();

    if (t < 64) {
        const float b = cb0[t];
        float a[EPB];
        #pragma unroll
        for (int r = 0; r < EPB; r++) a[r] = b;
        #pragma unroll 4
        for (int k = 0; k < 128; k += 4) {
            float4 w4;
            w4.x = cw0[(k + 0) * 64 + t];
            w4.y = cw0[(k + 1) * 64 + t];
            w4.z = cw0[(k + 2) * 64 + t];
            w4.w = cw0[(k + 3) * 64 + t];
            #pragma unroll
            for (int r = 0; r < EPB; r++) {
                const float4 v = *(const float4*)&s_ef[r][k];
                a[r] += v.x * w4.x + v.y * w4.y + v.z * w4.z + v.w * w4.w;
            }
        }
        #pragma unroll
        for (int r = 0; r < EPB; r++) s_h0[r][t] = fmaxf(a[r], 0.f);
    }
    __syncthreads();

    if (t < 32) {
        const float b = cb1[t];
        float a[EPB];
        #pragma unroll
        for (int r = 0; r < EPB; r++) a[r] = b;
        #pragma unroll 4
        for (int k = 0; k < 64; k += 4) {
            float4 w4;
            w4.x = cw1[(k + 0) * 32 + t];
            w4.y = cw1[(k + 1) * 32 + t];
            w4.z = cw1[(k + 2) * 32 + t];
            w4.w = cw1[(k + 3) * 32 + t];
            #pragma unroll
            for (int r = 0; r < EPB; r++) {
                const float4 v = *(const float4*)&s_h0[r][k];
                a[r] += v.x * w4.x + v.y * w4.y + v.z * w4.z + v.w * w4.w;
            }
        }
        #pragma unroll
        for (int r = 0; r < EPB; r++) s_h1[r][t] = fmaxf(a[r], 0.f);
    }
    __syncthreads();

    if (t < 32) {
        const float w2 = cw2[t];
        #pragma unroll
        for (int r = 0; r < EPB; r++) {
            float v = s_h1[r][t] * w2;
            #pragma unroll
            for (int off = 16; off > 0; off >>= 1)
                v += __shfl_down_sync(0xFFFFFFFFu, v, off);
            if (t == 0) out[eb + r] = v + cb2[0];
        }
    }
}

// ---------------------------------------------------------------------------
extern "C" void kernel_launch(void* const* d_in, const int* in_sizes, int n_in,
                              void* d_out, int out_size)
{
    const float* x    = (const float*)d_in[0];
    const float* ea   = (const float*)d_in[1];
    const int*   ei   = (const int*)  d_in[2];
    const float* new0 = (const float*)d_in[3];
    const float* neb0 = (const float*)d_in[4];
    const float* new1 = (const float*)d_in[5];
    const float* neb1 = (const float*)d_in[6];
    const float* eew0 = (const float*)d_in[7];
    const float* eeb0 = (const float*)d_in[8];
    const float* eew1 = (const float*)d_in[9];
    const float* eeb1 = (const float*)d_in[10];
    const float* mew0 = (const float*)d_in[11];
    const float* meb0 = (const float*)d_in[12];
    const float* mew1 = (const float*)d_in[13];
    const float* meb1 = (const float*)d_in[14];
    const float* mnw0 = (const float*)d_in[15];
    const float* mnb0 = (const float*)d_in[16];
    const float* cw0  = (const float*)d_in[17];
    const float* cb0  = (const float*)d_in[18];
    const float* cw1  = (const float*)d_in[19];
    const float* cb1  = (const float*)d_in[20];
    const float* cw2  = (const float*)d_in[21];
    const float* cb2  = (const float*)d_in[22];
    float* out = (float*)d_out;

    const int SMEM_BYTES = (64 * AP + 64 * 256) * 4 + 3 * BLK_E * 4;
    cudaFuncSetAttribute(mpn_step_kernel,
                         cudaFuncAttributeMaxDynamicSharedMemorySize, SMEM_BYTES);

    dup_weights<<<(768 * 64 + 255) / 256, 256>>>(mew0, mew1, mnw0);
    node_embed_kernel<<<NN / EPB, 128>>>(x, new0, neb0, new1, neb1);
    edge_embed_kernel<<<NE / EPB, 128>>>(ea, eew0, eeb0, eew1, eeb1);

    const int zgrid = (NN * ND + 255) / 256;
    const int mgrid = (NE + BLK_E - 1) / BLK_E;

    // step 0: in nf0, out A
    zero_nf_kernel<<<zgrid, 256>>>(0);
    mpn_step_kernel<<<mgrid, NTH, SMEM_BYTES>>>(ei, meb0, meb1, mnb0, 0, 1);
    // step 1: in A, out B
    zero_nf_kernel<<<zgrid, 256>>>(1);
    mpn_step_kernel<<<mgrid, NTH, SMEM_BYTES>>>(ei, meb0, meb1, mnb0, 1, 1);
    // step 2: in B, out A
    zero_nf_kernel<<<zgrid, 256>>>(0);
    mpn_step_kernel<<<mgrid, NTH, SMEM_BYTES>>>(ei, meb0, meb1, mnb0, 2, 1);
    // step 3: in A; final nf never consumed -> skip message/aggregation
    mpn_step_kernel<<<mgrid, NTH, SMEM_BYTES>>>(ei, meb0, meb1, mnb0, 3, 0);

    classify_kernel<<<NE / EPB, 128>>>(out, cw0, cb0, cw1, cb1, cw2, cb2);
}

// round 10
// speedup vs baseline: 1.4937x; 1.4937x over previous
#include <cuda_runtime.h>
#include <cuda_bf16.h>

#define NN 20000
#define NE 100000
#define ND 128
#define ED 128
#define EIN 291
#define HH 64
#define EPB 8          // for embed/classify kernels

// mpn_step GEMM config
#define BLK_E 128      // edges per block
#define NTH   256      // threads per block
#define AP    132      // A-tile row stride in floats (16B-aligned, conflict-free)

// Scratch (device globals; no allocation allowed)
__device__ float g_nf0[NN * ND];
__device__ float g_nfA[NN * ND];
__device__ float g_nfB[NN * ND];
__device__ float g_ef0[NE * ED];
__device__ float g_ef [NE * ED];
// step-invariant precomputed partial sums
__device__ float g_hc0[NE * 64];    // meb0 + nf0_i.W0i + nf0_j.W0j + ef0.W0e
__device__ float g_mc0[NE * 128];   // mnb0 + nf0_i.mnw0[0:128]

// ---------------------------------------------------------------------------
// f32x2 packed helpers (Blackwell FFMA2 path — PTX only)
// ---------------------------------------------------------------------------
__device__ __forceinline__ void fma2(unsigned long long& d,
                                     unsigned long long a, unsigned long long b) {
    asm("fma.rn.f32x2 %0, %1, %2, %0;" : "+l"(d) : "l"(a), "l"(b));
}
__device__ __forceinline__ unsigned long long pk2(float lo, float hi) {
    unsigned long long r;
    asm("mov.b64 %0, {%1, %2};" : "=l"(r) : "f"(lo), "f"(hi));
    return r;
}
__device__ __forceinline__ void upk2(float& lo, float& hi, unsigned long long v) {
    asm("mov.b64 {%0, %1}, %2;" : "=f"(lo), "=f"(hi) : "l"(v));
}

// ---------------------------------------------------------------------------
// Node embedding: nf0 = lin(relu(lin(x, new0)), new1)   [N,128]
// ---------------------------------------------------------------------------
__global__ void node_embed_kernel(const float* __restrict__ x,
                                  const float* __restrict__ w0, const float* __restrict__ b0,
                                  const float* __restrict__ w1, const float* __restrict__ b1)
{
    __shared__ float s_x[EPB][ND];
    __shared__ float s_h[EPB][ND];
    const int t = threadIdx.x;
    const int nb = blockIdx.x * EPB;

    #pragma unroll
    for (int r = 0; r < EPB; r++) s_x[r][t] = x[(nb + r) * ND + t];
    __syncthreads();

    float acc[EPB];
    {
        const float b = b0[t];
        #pragma unroll
        for (int r = 0; r < EPB; r++) acc[r] = b;
        #pragma unroll 4
        for (int k = 0; k < ND; k += 4) {
            float4 w4;
            w4.x = w0[(k + 0) * ND + t];
            w4.y = w0[(k + 1) * ND + t];
            w4.z = w0[(k + 2) * ND + t];
            w4.w = w0[(k + 3) * ND + t];
            #pragma unroll
            for (int r = 0; r < EPB; r++) {
                const float4 v = *(const float4*)&s_x[r][k];
                acc[r] += v.x * w4.x + v.y * w4.y + v.z * w4.z + v.w * w4.w;
            }
        }
        #pragma unroll
        for (int r = 0; r < EPB; r++) s_h[r][t] = fmaxf(acc[r], 0.f);
    }
    __syncthreads();
    {
        const float b = b1[t];
        #pragma unroll
        for (int r = 0; r < EPB; r++) acc[r] = b;
        #pragma unroll 4
        for (int k = 0; k < ND; k += 4) {
            float4 w4;
            w4.x = w1[(k + 0) * ND + t];
            w4.y = w1[(k + 1) * ND + t];
            w4.z = w1[(k + 2) * ND + t];
            w4.w = w1[(k + 3) * ND + t];
            #pragma unroll
            for (int r = 0; r < EPB; r++) {
                const float4 v = *(const float4*)&s_h[r][k];
                acc[r] += v.x * w4.x + v.y * w4.y + v.z * w4.z + v.w * w4.w;
            }
        }
        #pragma unroll
        for (int r = 0; r < EPB; r++) g_nf0[(nb + r) * ND + t] = acc[r];
    }
}

// ---------------------------------------------------------------------------
// Edge embedding: ef0 = lin(relu(lin(edge_attr, eew0)), eew1)   [E,128]
// ---------------------------------------------------------------------------
__global__ void edge_embed_kernel(const float* __restrict__ ea,
                                  const float* __restrict__ w0, const float* __restrict__ b0,
                                  const float* __restrict__ w1, const float* __restrict__ b1)
{
    __shared__ float s_in[EPB][EIN + 1];
    __shared__ float s_part[128][EPB + 1];
    __shared__ float s_h[EPB][HH];
    const int t = threadIdx.x;
    const int eb = blockIdx.x * EPB;

    #pragma unroll
    for (int r = 0; r < EPB; r++) {
        const float* row = ea + (size_t)(eb + r) * EIN;
        for (int k = t; k < EIN; k += 128) s_in[r][k] = row[k];
    }
    __syncthreads();

    const int c = t & 63, half = t >> 6;
    const int ks = half ? 146 : 0;
    const int ke = half ? EIN : 146;
    float acc[EPB];
    #pragma unroll
    for (int r = 0; r < EPB; r++) acc[r] = 0.f;
    for (int k = ks; k < ke; k++) {
        const float w = w0[k * HH + c];
        #pragma unroll
        for (int r = 0; r < EPB; r++) acc[r] += s_in[r][k] * w;
    }
    #pragma unroll
    for (int r = 0; r < EPB; r++) s_part[t][r] = acc[r];
    __syncthreads();

    if (t < HH) {
        const float b = b0[t];
        #pragma unroll
        for (int r = 0; r < EPB; r++)
            s_h[r][t] = fmaxf(s_part[t][r] + s_part[t + 64][r] + b, 0.f);
    }
    __syncthreads();

    {
        const float b = b1[t];
        float a2[EPB];
        #pragma unroll
        for (int r = 0; r < EPB; r++) a2[r] = b;
        #pragma unroll 4
        for (int k = 0; k < HH; k += 4) {
            float4 w4;
            w4.x = w1[(k + 0) * ED + t];
            w4.y = w1[(k + 1) * ED + t];
            w4.z = w1[(k + 2) * ED + t];
            w4.w = w1[(k + 3) * ED + t];
            #pragma unroll
            for (int r = 0; r < EPB; r++) {
                const float4 v = *(const float4*)&s_h[r][k];
                a2[r] += v.x * w4.x + v.y * w4.y + v.z * w4.z + v.w * w4.w;
            }
        }
        #pragma unroll
        for (int r = 0; r < EPB; r++) {
            const int e = eb + r;
            g_ef0[e * ED + t] = a2[r];
            g_ef [e * ED + t] = a2[r];
        }
    }
}

// ---------------------------------------------------------------------------
__global__ void zero_nf_kernel(int sel)
{
    float* p = sel ? g_nfB : g_nfA;
    const int i = blockIdx.x * blockDim.x + threadIdx.x;
    if (i < NN * ND) p[i] = 0.f;
}

// ---------------------------------------------------------------------------
// Shared GEMM building blocks (R7 dataflow)
// ---------------------------------------------------------------------------
__device__ __forceinline__ void gather_chunk_T(float* sA, const float* __restrict__ src,
                                               const int* ridx, int koff, int t)
{
    const int ge = t & 127, gh = t >> 7;
    const int row = ridx[ge];
    const float4* p = (const float4*)(src + (size_t)row * 128 + koff + gh * 32);
    #pragma unroll
    for (int q = 0; q < 8; q++) {
        const float4 v = p[q];
        float* d = sA + (gh * 32 + q * 4) * AP + ge;
        d[0] = v.x; d[AP] = v.y; d[2 * AP] = v.z; d[3 * AP] = v.w;
    }
}

__device__ __forceinline__ void stage_B64(float* sB, const float* __restrict__ w, int t)
{
    const float4* s = (const float4*)w;
    float4* d = (float4*)sB;
    #pragma unroll
    for (int r = 0; r < 4; r++) d[t + r * NTH] = s[t + r * NTH];
}

__device__ __forceinline__ void stage_B128(float* sB, const float* __restrict__ w, int t)
{
    const float4* s = (const float4*)w;
    float4* d = (float4*)sB;
    #pragma unroll
    for (int r = 0; r < 8; r++) d[t + r * NTH] = s[t + r * NTH];
}

__device__ __forceinline__ void gemm64(unsigned long long acc[4][4],
                                       const float* sA, const float* sB,
                                       int e0, int cg)
{
    #pragma unroll 4
    for (int kk = 0; kk < 64; kk++) {
        const ulonglong2 a01 = *(const ulonglong2*)(sA + kk * AP + e0);
        const ulonglong2 a23 = *(const ulonglong2*)(sA + kk * AP + e0 + 4);
        const unsigned long long av[4] = {a01.x, a01.y, a23.x, a23.y};
        const float4 w = *(const float4*)(sB + kk * 64 + cg * 4);
        const unsigned long long wv[4] =
            {pk2(w.x, w.x), pk2(w.y, w.y), pk2(w.z, w.z), pk2(w.w, w.w)};
        #pragma unroll
        for (int p = 0; p < 4; p++)
            #pragma unroll
            for (int c = 0; c < 4; c++)
                fma2(acc[p][c], av[p], wv[c]);
    }
}

__device__ __forceinline__ void gemm128(unsigned long long acc[4][8],
                                        const float* sA, const float* sB,
                                        int e0, int cg)
{
    #pragma unroll 2
    for (int kk = 0; kk < 64; kk++) {
        const ulonglong2 a01 = *(const ulonglong2*)(sA + kk * AP + e0);
        const ulonglong2 a23 = *(const ulonglong2*)(sA + kk * AP + e0 + 4);
        const unsigned long long av[4] = {a01.x, a01.y, a23.x, a23.y};
        const float4 w0 = *(const float4*)(sB + kk * 128 + cg * 8);
        const float4 w1 = *(const float4*)(sB + kk * 128 + cg * 8 + 4);
        const unsigned long long wv[8] =
            {pk2(w0.x, w0.x), pk2(w0.y, w0.y), pk2(w0.z, w0.z), pk2(w0.w, w0.w),
             pk2(w1.x, w1.x), pk2(w1.y, w1.y), pk2(w1.z, w1.z), pk2(w1.w, w1.w)};
        #pragma unroll
        for (int p = 0; p < 4; p++)
            #pragma unroll
            for (int c = 0; c < 8; c++)
                fma2(acc[p][c], av[p], wv[c]);
    }
}

// ---------------------------------------------------------------------------
// Precompute step-invariant partials:
//   hc0[e] = meb0 + nf0_i.W0(rows 0-127) + nf0_j.W0(rows 256-383) + ef0.W0(rows 512-639)
//   mc0[e] = mnb0 + nf0_i.mnw0(rows 0-127)
// Raw sums, NO relu.
// ---------------------------------------------------------------------------
__global__ void __launch_bounds__(NTH)
precompute_static_kernel(const int* __restrict__ ei,
                         const float* __restrict__ mew0, const float* __restrict__ meb0,
                         const float* __restrict__ mnw0, const float* __restrict__ mnb0)
{
    extern __shared__ float smf[];
    float* sA  = smf;
    float* sB  = smf + 64 * AP;
    int*   sRi = (int*)(sB + 64 * 128);
    int*   sRj = sRi + BLK_E;
    int*   sRe = sRj + BLK_E;

    const int t  = threadIdx.x;
    const int eb = blockIdx.x * BLK_E;
    const int cg = t & 15;
    const int eg = t >> 4;
    const int e0 = eg * 8;

    if (t < BLK_E) {
        int e = eb + t; if (e > NE - 1) e = NE - 1;
        sRe[t] = e;
        sRj[t] = ei[e];
        sRi[t] = ei[NE + e];
    }

    // ---- hc0: 6 static chunks, orig chunk ids {0,1,4,5,8,9} ----
    unsigned long long acc1[4][4];
    #pragma unroll
    for (int c = 0; c < 4; c++) {
        const float b = meb0[cg * 4 + c];
        const unsigned long long bp = pk2(b, b);
        #pragma unroll
        for (int p = 0; p < 4; p++) acc1[p][c] = bp;
    }
    #pragma unroll 1
    for (int ci = 0; ci < 6; ci++) {
        __syncthreads();
        const float* src; const int* ridx;
        if (ci < 2)      { src = g_nf0; ridx = sRi; }
        else if (ci < 4) { src = g_nf0; ridx = sRj; }
        else             { src = g_ef0; ridx = sRe; }
        gather_chunk_T(sA, src, ridx, (ci & 1) * 64, t);
        const int oc = (ci >> 1) * 4 + (ci & 1);   // 0,1,4,5,8,9
        stage_B64(sB, mew0 + (size_t)oc * 64 * 64, t);
        __syncthreads();
        gemm64(acc1, sA, sB, e0, cg);
    }
    // store raw partials
    #pragma unroll
    for (int p = 0; p < 4; p++) {
        float lo[4], hi[4];
        #pragma unroll
        for (int c = 0; c < 4; c++) upk2(lo[c], hi[c], acc1[p][c]);
        const int el0 = e0 + 2 * p;
        if (eb + el0 < NE)
            *(float4*)(g_hc0 + (size_t)(eb + el0) * 64 + cg * 4) =
                make_float4(lo[0], lo[1], lo[2], lo[3]);
        if (eb + el0 + 1 < NE)
            *(float4*)(g_hc0 + (size_t)(eb + el0 + 1) * 64 + cg * 4) =
                make_float4(hi[0], hi[1], hi[2], hi[3]);
    }

    // ---- mc0: nf0_i with mnw0 rows 0-127 (2 chunks), 128 cols ----
    unsigned long long acc3[4][8];
    #pragma unroll
    for (int c = 0; c < 8; c++) {
        const float b = mnb0[cg * 8 + c];
        const unsigned long long bp = pk2(b, b);
        #pragma unroll
        for (int p = 0; p < 4; p++) acc3[p][c] = bp;
    }
    #pragma unroll 1
    for (int ci = 0; ci < 2; ci++) {
        __syncthreads();
        gather_chunk_T(sA, g_nf0, sRi, ci * 64, t);
        stage_B128(sB, mnw0 + (size_t)ci * 64 * 128, t);
        __syncthreads();
        gemm128(acc3, sA, sB, e0, cg);
    }
    #pragma unroll
    for (int p = 0; p < 4; p++) {
        float lo[8], hi[8];
        #pragma unroll
        for (int c = 0; c < 8; c++) upk2(lo[c], hi[c], acc3[p][c]);
        const int el0 = e0 + 2 * p;
        if (eb + el0 < NE) {
            float4* d = (float4*)(g_mc0 + (size_t)(eb + el0) * 128 + cg * 8);
            d[0] = make_float4(lo[0], lo[1], lo[2], lo[3]);
            d[1] = make_float4(lo[4], lo[5], lo[6], lo[7]);
        }
        if (eb + el0 + 1 < NE) {
            float4* d = (float4*)(g_mc0 + (size_t)(eb + el0 + 1) * 128 + cg * 8);
            d[0] = make_float4(hi[0], hi[1], hi[2], hi[3]);
            d[1] = make_float4(hi[4], hi[5], hi[6], hi[7]);
        }
    }
}

// ---------------------------------------------------------------------------
// One message-passing step (dynamic parts only; acc seeded from hc0/mc0).
//   phase: 0: nf_in=g_nf0 out A | 1: in A out B | 2: in B out A | 3: in A
// ---------------------------------------------------------------------------
__global__ void __launch_bounds__(NTH)
mpn_step_kernel(const int* __restrict__ ei,
                const float* __restrict__ mew0,
                const float* __restrict__ mew1, const float* __restrict__ meb1,
                const float* __restrict__ mnw0,
                int phase, int compute_msg)
{
    extern __shared__ float smf[];
    float* sA  = smf;                       // [64][AP] transposed A chunk
    float* sB  = smf + 64 * AP;             // [64][128] max
    int*   sRi = (int*)(sB + 64 * 128);
    int*   sRj = sRi + BLK_E;
    int*   sRe = sRj + BLK_E;

    const float* __restrict__ nf_in =
        (phase == 0) ? g_nf0 : ((phase & 1) ? g_nfA : g_nfB);
    float* __restrict__ nf_out = (phase & 1) ? g_nfB : g_nfA;

    const int t  = threadIdx.x;
    const int eb = blockIdx.x * BLK_E;
    const int cg = t & 15;
    const int eg = t >> 4;
    const int e0 = eg * 8;

    if (t < BLK_E) {
        int e = eb + t; if (e > NE - 1) e = NE - 1;
        sRe[t] = e;
        sRj[t] = ei[e];
        sRi[t] = ei[NE + e];
    }

    // ====== Phase 1: h = relu(hc0 + dynamic @ mew0), 64 cols ======
    unsigned long long acc1[4][4];
    #pragma unroll
    for (int p = 0; p < 4; p++) {
        int ea_ = eb + e0 + 2 * p;     if (ea_ > NE - 1) ea_ = NE - 1;
        int eb_ = eb + e0 + 2 * p + 1; if (eb_ > NE - 1) eb_ = NE - 1;
        const float4 fa = *(const float4*)(g_hc0 + (size_t)ea_ * 64 + cg * 4);
        const float4 fb = *(const float4*)(g_hc0 + (size_t)eb_ * 64 + cg * 4);
        acc1[p][0] = pk2(fa.x, fb.x);
        acc1[p][1] = pk2(fa.y, fb.y);
        acc1[p][2] = pk2(fa.z, fb.z);
        acc1[p][3] = pk2(fa.w, fb.w);
    }

    #pragma unroll 1
    for (int ci = 0; ci < 6; ci++) {
        __syncthreads();
        const float* src; const int* ridx;
        if (ci < 2)      { src = nf_in; ridx = sRi; }
        else if (ci < 4) { src = nf_in; ridx = sRj; }
        else             { src = g_ef;  ridx = sRe; }
        gather_chunk_T(sA, src, ridx, (ci & 1) * 64, t);
        const int oc = (ci >> 1) * 4 + 2 + (ci & 1);  // 2,3,6,7,10,11
        stage_B64(sB, mew0 + (size_t)oc * 64 * 64, t);
        __syncthreads();
        gemm64(acc1, sA, sB, e0, cg);
    }

    // epilogue: relu(h) -> sA transposed [hcol][edge]; stage mew1 full
    __syncthreads();
    #pragma unroll
    for (int p = 0; p < 4; p++)
        #pragma unroll
        for (int c = 0; c < 4; c++) {
            float lo, hi; upk2(lo, hi, acc1[p][c]);
            sA[(cg * 4 + c) * AP + e0 + 2 * p]     = fmaxf(lo, 0.f);
            sA[(cg * 4 + c) * AP + e0 + 2 * p + 1] = fmaxf(hi, 0.f);
        }
    stage_B128(sB, mew1, t);
    __syncthreads();

    // ====== Phase 2: ef = relu(h @ mew1 + meb1), 128 cols ======
    unsigned long long acc2[4][8];
    #pragma unroll
    for (int c = 0; c < 8; c++) {
        const float b = meb1[cg * 8 + c];
        const unsigned long long bp = pk2(b, b);
        #pragma unroll
        for (int p = 0; p < 4; p++) acc2[p][c] = bp;
    }
    gemm128(acc2, sA, sB, e0, cg);
    #pragma unroll
    for (int p = 0; p < 4; p++) {
        float lo[8], hi[8];
        #pragma unroll
        for (int c = 0; c < 8; c++) {
            upk2(lo[c], hi[c], acc2[p][c]);
            lo[c] = fmaxf(lo[c], 0.f);
            hi[c] = fmaxf(hi[c], 0.f);
        }
        const int el0 = e0 + 2 * p;
        if (eb + el0 < NE) {
            float4* d = (float4*)(g_ef + (size_t)(eb + el0) * 128 + cg * 8);
            d[0] = make_float4(lo[0], lo[1], lo[2], lo[3]);
            d[1] = make_float4(lo[4], lo[5], lo[6], lo[7]);
        }
        if (eb + el0 + 1 < NE) {
            float4* d = (float4*)(g_ef + (size_t)(eb + el0 + 1) * 128 + cg * 8);
            d[0] = make_float4(hi[0], hi[1], hi[2], hi[3]);
            d[1] = make_float4(hi[4], hi[5], hi[6], hi[7]);
        }
    }

    if (!compute_msg) return;

    // ====== Phase 3: msg = relu(mc0 + [nf_in_i | ef] @ mnw0); scatter ======
    unsigned long long acc3[4][8];
    #pragma unroll
    for (int p = 0; p < 4; p++) {
        int ea_ = eb + e0 + 2 * p;     if (ea_ > NE - 1) ea_ = NE - 1;
        int eb_ = eb + e0 + 2 * p + 1; if (eb_ > NE - 1) eb_ = NE - 1;
        const float4* pa = (const float4*)(g_mc0 + (size_t)ea_ * 128 + cg * 8);
        const float4* pb = (const float4*)(g_mc0 + (size_t)eb_ * 128 + cg * 8);
        const float4 a0 = pa[0], a1 = pa[1], b0 = pb[0], b1 = pb[1];
        acc3[p][0] = pk2(a0.x, b0.x); acc3[p][1] = pk2(a0.y, b0.y);
        acc3[p][2] = pk2(a0.z, b0.z); acc3[p][3] = pk2(a0.w, b0.w);
        acc3[p][4] = pk2(a1.x, b1.x); acc3[p][5] = pk2(a1.y, b1.y);
        acc3[p][6] = pk2(a1.z, b1.z); acc3[p][7] = pk2(a1.w, b1.w);
    }
    #pragma unroll 1
    for (int ci = 0; ci < 4; ci++) {
        __syncthreads();
        const float* src; const int* ridx;
        if (ci < 2) { src = nf_in; ridx = sRi; }
        else        { src = g_ef;  ridx = sRe; }
        gather_chunk_T(sA, src, ridx, (ci & 1) * 64, t);
        stage_B128(sB, mnw0 + (size_t)(ci + 2) * 64 * 128, t);
        __syncthreads();
        gemm128(acc3, sA, sB, e0, cg);
    }
    #pragma unroll
    for (int p = 0; p < 4; p++) {
        float lo[8], hi[8];
        #pragma unroll
        for (int c = 0; c < 8; c++) {
            upk2(lo[c], hi[c], acc3[p][c]);
            lo[c] = fmaxf(lo[c], 0.f);
            hi[c] = fmaxf(hi[c], 0.f);
        }
        const int el0 = e0 + 2 * p;
        if (eb + el0 < NE) {
            float* dst = nf_out + (size_t)sRi[el0] * 128 + cg * 8;
            #pragma unroll
            for (int c = 0; c < 8; c++) atomicAdd(dst + c, lo[c]);
        }
        if (eb + el0 + 1 < NE) {
            float* dst = nf_out + (size_t)sRi[el0 + 1] * 128 + cg * 8;
            #pragma unroll
            for (int c = 0; c < 8; c++) atomicAdd(dst + c, hi[c]);
        }
    }
}

// ---------------------------------------------------------------------------
// Classifier: out = lin(relu(lin(relu(lin(ef, cw0)), cw1)), cw2)  [E,1]
// ---------------------------------------------------------------------------
__global__ void classify_kernel(float* __restrict__ out,
                                const float* __restrict__ cw0, const float* __restrict__ cb0,
                                const float* __restrict__ cw1, const float* __restrict__ cb1,
                                const float* __restrict__ cw2, const float* __restrict__ cb2)
{
    __shared__ float s_ef[EPB][ED];
    __shared__ float s_h0[EPB][64];
    __shared__ float s_h1[EPB][32];
    const int t = threadIdx.x;
    const int eb = blockIdx.x * EPB;

    #pragma unroll
    for (int r = 0; r < EPB; r++) s_ef[r][t] = g_ef[(eb + r) * ED + t];
    __syncthreads();

    if (t < 64) {
        const float b = cb0[t];
        float a[EPB];
        #pragma unroll
        for (int r = 0; r < EPB; r++) a[r] = b;
        #pragma unroll 4
        for (int k = 0; k < 128; k += 4) {
            float4 w4;
            w4.x = cw0[(k + 0) * 64 + t];
            w4.y = cw0[(k + 1) * 64 + t];
            w4.z = cw0[(k + 2) * 64 + t];
            w4.w = cw0[(k + 3) * 64 + t];
            #pragma unroll
            for (int r = 0; r < EPB; r++) {
                const float4 v = *(const float4*)&s_ef[r][k];
                a[r] += v.x * w4.x + v.y * w4.y + v.z * w4.z + v.w * w4.w;
            }
        }
        #pragma unroll
        for (int r = 0; r < EPB; r++) s_h0[r][t] = fmaxf(a[r], 0.f);
    }
    __syncthreads();

    if (t < 32) {
        const float b = cb1[t];
        float a[EPB];
        #pragma unroll
        for (int r = 0; r < EPB; r++) a[r] = b;
        #pragma unroll 4
        for (int k = 0; k < 64; k += 4) {
            float4 w4;
            w4.x = cw1[(k + 0) * 32 + t];
            w4.y = cw1[(k + 1) * 32 + t];
            w4.z = cw1[(k + 2) * 32 + t];
            w4.w = cw1[(k + 3) * 32 + t];
            #pragma unroll
            for (int r = 0; r < EPB; r++) {
                const float4 v = *(const float4*)&s_h0[r][k];
                a[r] += v.x * w4.x + v.y * w4.y + v.z * w4.z + v.w * w4.w;
            }
        }
        #pragma unroll
        for (int r = 0; r < EPB; r++) s_h1[r][t] = fmaxf(a[r], 0.f);
    }
    __syncthreads();

    if (t < 32) {
        const float w2 = cw2[t];
        #pragma unroll
        for (int r = 0; r < EPB; r++) {
            float v = s_h1[r][t] * w2;
            #pragma unroll
            for (int off = 16; off > 0; off >>= 1)
                v += __shfl_down_sync(0xFFFFFFFFu, v, off);
            if (t == 0) out[eb + r] = v + cb2[0];
        }
    }
}

// ---------------------------------------------------------------------------
extern "C" void kernel_launch(void* const* d_in, const int* in_sizes, int n_in,
                              void* d_out, int out_size)
{
    const float* x    = (const float*)d_in[0];
    const float* ea   = (const float*)d_in[1];
    const int*   ei   = (const int*)  d_in[2];
    const float* new0 = (const float*)d_in[3];
    const float* neb0 = (const float*)d_in[4];
    const float* new1 = (const float*)d_in[5];
    const float* neb1 = (const float*)d_in[6];
    const float* eew0 = (const float*)d_in[7];
    const float* eeb0 = (const float*)d_in[8];
    const float* eew1 = (const float*)d_in[9];
    const float* eeb1 = (const float*)d_in[10];
    const float* mew0 = (const float*)d_in[11];
    const float* meb0 = (const float*)d_in[12];
    const float* mew1 = (const float*)d_in[13];
    const float* meb1 = (const float*)d_in[14];
    const float* mnw0 = (const float*)d_in[15];
    const float* mnb0 = (const float*)d_in[16];
    const float* cw0  = (const float*)d_in[17];
    const float* cb0  = (const float*)d_in[18];
    const float* cw1  = (const float*)d_in[19];
    const float* cb1  = (const float*)d_in[20];
    const float* cw2  = (const float*)d_in[21];
    const float* cb2  = (const float*)d_in[22];
    float* out = (float*)d_out;

    const int SMEM_BYTES = (64 * AP + 64 * 128) * 4 + 3 * BLK_E * 4;
    cudaFuncSetAttribute(mpn_step_kernel,
                         cudaFuncAttributeMaxDynamicSharedMemorySize, SMEM_BYTES);
    cudaFuncSetAttribute(precompute_static_kernel,
                         cudaFuncAttributeMaxDynamicSharedMemorySize, SMEM_BYTES);

    node_embed_kernel<<<NN / EPB, 128>>>(x, new0, neb0, new1, neb1);
    edge_embed_kernel<<<NE / EPB, 128>>>(ea, eew0, eeb0, eew1, eeb1);

    const int zgrid = (NN * ND + 255) / 256;
    const int mgrid = (NE + BLK_E - 1) / BLK_E;

    precompute_static_kernel<<<mgrid, NTH, SMEM_BYTES>>>(ei, mew0, meb0, mnw0, mnb0);

    // step 0: in nf0, out A
    zero_nf_kernel<<<zgrid, 256>>>(0);
    mpn_step_kernel<<<mgrid, NTH, SMEM_BYTES>>>(ei, mew0, mew1, meb1, mnw0, 0, 1);
    // step 1: in A, out B
    zero_nf_kernel<<<zgrid, 256>>>(1);
    mpn_step_kernel<<<mgrid, NTH, SMEM_BYTES>>>(ei, mew0, mew1, meb1, mnw0, 1, 1);
    // step 2: in B, out A
    zero_nf_kernel<<<zgrid, 256>>>(0);
    mpn_step_kernel<<<mgrid, NTH, SMEM_BYTES>>>(ei, mew0, mew1, meb1, mnw0, 2, 1);
    // step 3: in A; final nf never consumed -> skip message/aggregation
    mpn_step_kernel<<<mgrid, NTH, SMEM_BYTES>>>(ei, mew0, mew1, meb1, mnw0, 3, 0);

    classify_kernel<<<NE / EPB, 128>>>(out, cw0, cb0, cw1, cb1, cw2, cb2);
}